// round 1
// baseline (speedup 1.0000x reference)
#include <cuda_runtime.h>
#include <cstdint>

#define N_NODES 50000
#define N_EDGES 1600000

typedef unsigned long long u64;

// ---------------- scratch (static device globals; no allocation) ----------------
__device__ float g_hx[(size_t)N_NODES * 64];   // x @ fR_W1[0:16,:]  + fR_b1
__device__ float g_hs[(size_t)N_NODES * 64];   // x @ fR_W1[16:32,:]
__device__ float g_gx[(size_t)N_NODES * 64];   // x @ fO_W1[0:16,:]  + fO_b1
__device__ float g_agg[(size_t)N_NODES * 16];  // scatter-sum of e_new
__device__ int   g_is64;                       // edge_index dtype probe result

// ---------------- packed f32x2 helpers (Blackwell FFMA2) ----------------
__device__ __forceinline__ u64 ffma2(u64 a, u64 b, u64 c) {
    u64 d;
    asm("fma.rn.f32x2 %0, %1, %2, %3;" : "=l"(d) : "l"(a), "l"(b), "l"(c));
    return d;
}
__device__ __forceinline__ u64 dup2(float a) {
    u64 r; asm("mov.b64 %0, {%1, %1};" : "=l"(r) : "f"(a)); return r;
}
__device__ __forceinline__ float2 unpk(u64 a) {
    float2 f; asm("mov.b64 {%0, %1}, %2;" : "=f"(f.x), "=f"(f.y) : "l"(a)); return f;
}
__device__ __forceinline__ u64 pk(float x, float y) {
    u64 r; asm("mov.b64 %0, {%1, %2};" : "=l"(r) : "f"(x), "f"(y)); return r;
}
__device__ __forceinline__ void lds2(u64 &a, u64 &b, unsigned addr) {
    asm("ld.shared.v2.u64 {%0, %1}, [%2];" : "=l"(a), "=l"(b) : "r"(addr));
}
__device__ __forceinline__ unsigned sptr(const void *p) {
    return (unsigned)__cvta_generic_to_shared(p);
}

// ---------------- probe: is edge_index int64 or int32? ----------------
__global__ void probe_kernel(const int *__restrict__ ei32) {
    __shared__ int ok;
    if (threadIdx.x == 0) ok = 1;
    __syncthreads();
    // If buffer is little-endian int64 with values < 50000, every odd 32-bit
    // word is zero. If it is int32, odd words are random node ids (nonzero whp).
    int w = ei32[threadIdx.x * 2 + 1];
    if (w != 0) ok = 0;
    __syncthreads();
    if (threadIdx.x == 0) g_is64 = ok;
}

// ---------------- shared MLP body: h[64] (+= a[16] @ W1c) -> relu -> out = h @ W2 + b2 ----
// H: 32 packed f32x2 accumulators pre-initialized with the gathered/bias part.
// av: 16 scalar inputs. wb1: smem addr of W1c[16][64]. wb2: smem addr of W2[64][16].
// bb: smem addr of b2[16]. O: 8 packed f32x2 outputs (16 floats).
__device__ __forceinline__ void mlp64(u64 *H, const float *av,
                                      unsigned wb1, unsigned wb2, unsigned bb,
                                      u64 *O) {
#pragma unroll
    for (int k = 0; k < 16; k++) {
        u64 a2 = dup2(av[k]);
#pragma unroll
        for (int t = 0; t < 16; t++) {
            u64 w0, w1;
            lds2(w0, w1, wb1 + k * 256 + t * 16);
            H[2 * t]     = ffma2(a2, w0, H[2 * t]);
            H[2 * t + 1] = ffma2(a2, w1, H[2 * t + 1]);
        }
    }
#pragma unroll
    for (int m = 0; m < 32; m++) {
        float2 v = unpk(H[m]);
        H[m] = pk(fmaxf(v.x, 0.f), fmaxf(v.y, 0.f));
    }
#pragma unroll
    for (int c = 0; c < 4; c++) lds2(O[2 * c], O[2 * c + 1], bb + 16 * c);
#pragma unroll
    for (int m = 0; m < 32; m++) {
        float2 hv = unpk(H[m]);
        u64 a0 = dup2(hv.x);
#pragma unroll
        for (int c = 0; c < 4; c++) {
            u64 w0, w1;
            lds2(w0, w1, wb2 + (2 * m) * 64 + c * 16);
            O[2 * c]     = ffma2(a0, w0, O[2 * c]);
            O[2 * c + 1] = ffma2(a0, w1, O[2 * c + 1]);
        }
        u64 a1 = dup2(hv.y);
#pragma unroll
        for (int c = 0; c < 4; c++) {
            u64 w0, w1;
            lds2(w0, w1, wb2 + (2 * m + 1) * 64 + c * 16);
            O[2 * c]     = ffma2(a1, w0, O[2 * c]);
            O[2 * c + 1] = ffma2(a1, w1, O[2 * c + 1]);
        }
    }
}

// ---------------- precompute: node tables + zero agg ----------------
__global__ void __launch_bounds__(128) pre_kernel(
    const float *__restrict__ x,
    const float *__restrict__ fR_W1, const float *__restrict__ fR_b1,
    const float *__restrict__ fO_W1, const float *__restrict__ fO_b1) {
    const int gtid = blockIdx.x * 128 + threadIdx.x;
    if (gtid < N_NODES * 16 / 4)
        ((float4 *)g_agg)[gtid] = make_float4(0.f, 0.f, 0.f, 0.f);
    if (gtid >= N_NODES * 12) return;

    const int n = gtid / 12;
    const int r = gtid - n * 12;
    const int table = r >> 2;   // 0:hx 1:hs 2:gx
    const int ch = r & 3;       // 16-col chunk

    float xv[16];
    {
        const float4 *x4 = (const float4 *)x;
#pragma unroll
        for (int q = 0; q < 4; q++) {
            float4 v = x4[(long long)n * 4 + q];
            xv[4 * q] = v.x; xv[4 * q + 1] = v.y; xv[4 * q + 2] = v.z; xv[4 * q + 3] = v.w;
        }
    }
    const float *W; const float *bias; float *out; float bs;
    if (table == 0)      { W = fR_W1;            bias = fR_b1; out = g_hx; bs = 1.f; }
    else if (table == 1) { W = fR_W1 + 16 * 64;  bias = fR_b1; out = g_hs; bs = 0.f; }
    else                 { W = fO_W1;            bias = fO_b1; out = g_gx; bs = 1.f; }

    float acc[16];
    {
        const float4 *b4 = (const float4 *)(bias + ch * 16);
#pragma unroll
        for (int q = 0; q < 4; q++) {
            float4 v = b4[q];
            acc[4 * q] = v.x * bs; acc[4 * q + 1] = v.y * bs;
            acc[4 * q + 2] = v.z * bs; acc[4 * q + 3] = v.w * bs;
        }
    }
#pragma unroll
    for (int k = 0; k < 16; k++) {
        const float4 *wr = (const float4 *)(W + k * 64 + ch * 16);
#pragma unroll
        for (int q = 0; q < 4; q++) {
            float4 w = wr[q];
            acc[4 * q]     += xv[k] * w.x;
            acc[4 * q + 1] += xv[k] * w.y;
            acc[4 * q + 2] += xv[k] * w.z;
            acc[4 * q + 3] += xv[k] * w.w;
        }
    }
    float4 *o4 = (float4 *)(out + (long long)n * 64 + ch * 16);
#pragma unroll
    for (int q = 0; q < 4; q++) {
        float4 v;
        v.x = acc[4 * q]; v.y = acc[4 * q + 1]; v.z = acc[4 * q + 2]; v.w = acc[4 * q + 3];
        o4[q] = v;
    }
}

// ---------------- edge kernel: fR MLP + scatter ----------------
__global__ void __launch_bounds__(128) edge_kernel(
    const long long *__restrict__ ei64,
    const float *__restrict__ e,
    const float *__restrict__ fR_W1,
    const float *__restrict__ fR_W2,
    const float *__restrict__ fR_b2,
    float *__restrict__ outE) {
    __shared__ float sW1c[1024];        // fR_W1 rows 32..47  (e part)
    __shared__ float sW2[1024];         // fR_W2 [64][16]
    __shared__ float sB2[16];
    __shared__ int sDst[128];
    __shared__ int sSrc[128];
    __shared__ float sH[128 * 68];      // padded rows: 272 B pitch

    const int tid = threadIdx.x;
    {
        const float4 *w1 = (const float4 *)(fR_W1 + 32 * 64);
        const float4 *w2 = (const float4 *)fR_W2;
        ((float4 *)sW1c)[tid] = w1[tid];
        ((float4 *)sW1c)[tid + 128] = w1[tid + 128];
        ((float4 *)sW2)[tid] = w2[tid];
        ((float4 *)sW2)[tid + 128] = w2[tid + 128];
        if (tid < 16) sB2[tid] = fR_b2[tid];
    }
    const long long eidx = (long long)blockIdx.x * 128 + tid;
    int src, dst;
    if (g_is64) {
        src = (int)ei64[eidx];
        dst = (int)ei64[N_EDGES + eidx];
    } else {
        const int *ei32 = (const int *)ei64;
        src = ei32[eidx];
        dst = ei32[N_EDGES + eidx];
    }
    sDst[tid] = dst;
    sSrc[tid] = src;
    __syncthreads();

    // cooperative gather: sH[el] = hx[dst[el]] + hs[src[el]]  (b1 already folded in hx)
    const float4 *hx4 = (const float4 *)g_hx;
    const float4 *hs4 = (const float4 *)g_hs;
#pragma unroll
    for (int it = 0; it < 16; ++it) {
        int idx = tid + it * 128;
        int el = idx >> 4, ch = idx & 15;
        float4 a = hx4[(long long)sDst[el] * 16 + ch];
        float4 b = hs4[(long long)sSrc[el] * 16 + ch];
        float4 s;
        s.x = a.x + b.x; s.y = a.y + b.y; s.z = a.z + b.z; s.w = a.w + b.w;
        *(float4 *)&sH[el * 68 + ch * 4] = s;
    }
    __syncthreads();

    u64 H[32];
    {
        unsigned hb = sptr(&sH[tid * 68]);
#pragma unroll
        for (int t = 0; t < 16; t++) lds2(H[2 * t], H[2 * t + 1], hb + 16 * t);
    }
    float ev[16];
    {
        const float4 *E4 = (const float4 *)e;
#pragma unroll
        for (int q = 0; q < 4; q++) {
            float4 v = E4[eidx * 4 + q];
            ev[4 * q] = v.x; ev[4 * q + 1] = v.y; ev[4 * q + 2] = v.z; ev[4 * q + 3] = v.w;
        }
    }
    u64 O[8];
    mlp64(H, ev, sptr(sW1c), sptr(sW2), sptr(sB2), O);

    float o[16];
#pragma unroll
    for (int p = 0; p < 8; p++) {
        float2 v = unpk(O[p]);
        o[2 * p] = v.x; o[2 * p + 1] = v.y;
    }
    float4 *oE4 = (float4 *)outE;
#pragma unroll
    for (int q = 0; q < 4; q++) {
        float4 v;
        v.x = o[4 * q]; v.y = o[4 * q + 1]; v.z = o[4 * q + 2]; v.w = o[4 * q + 3];
        oE4[eidx * 4 + q] = v;
    }
    float *aggp = g_agg + (long long)dst * 16;
#pragma unroll
    for (int c = 0; c < 16; c++) atomicAdd(aggp + c, o[c]);
}

// ---------------- node kernel: fO MLP ----------------
__global__ void __launch_bounds__(128) node_kernel(
    const float *__restrict__ fO_W1,
    const float *__restrict__ fO_W2,
    const float *__restrict__ fO_b2,
    float *__restrict__ outX) {
    __shared__ float sW1c[1024];    // fO_W1 rows 16..31 (agg part)
    __shared__ float sW2[1024];
    __shared__ float sB2[16];
    const int tid = threadIdx.x;
    {
        const float4 *w1 = (const float4 *)(fO_W1 + 16 * 64);
        const float4 *w2 = (const float4 *)fO_W2;
        ((float4 *)sW1c)[tid] = w1[tid];
        ((float4 *)sW1c)[tid + 128] = w1[tid + 128];
        ((float4 *)sW2)[tid] = w2[tid];
        ((float4 *)sW2)[tid + 128] = w2[tid + 128];
        if (tid < 16) sB2[tid] = fO_b2[tid];
    }
    __syncthreads();
    const int n = blockIdx.x * 128 + tid;
    if (n >= N_NODES) return;

    u64 H[32];
    {
        const float4 *gx4 = (const float4 *)g_gx;
#pragma unroll
        for (int t = 0; t < 16; t++) {
            float4 v = gx4[(long long)n * 16 + t];
            H[2 * t] = pk(v.x, v.y);
            H[2 * t + 1] = pk(v.z, v.w);
        }
    }
    float av[16];
    {
        const float4 *a4 = (const float4 *)g_agg;
#pragma unroll
        for (int q = 0; q < 4; q++) {
            float4 v = a4[(long long)n * 4 + q];
            av[4 * q] = v.x; av[4 * q + 1] = v.y; av[4 * q + 2] = v.z; av[4 * q + 3] = v.w;
        }
    }
    u64 O[8];
    mlp64(H, av, sptr(sW1c), sptr(sW2), sptr(sB2), O);

    float4 *oX4 = (float4 *)outX;
#pragma unroll
    for (int q = 0; q < 4; q++) {
        float2 v0 = unpk(O[2 * q]);
        float2 v1 = unpk(O[2 * q + 1]);
        float4 v;
        v.x = v0.x; v.y = v0.y; v.z = v1.x; v.w = v1.y;
        oX4[(long long)n * 4 + q] = v;
    }
}

// ---------------- launch ----------------
extern "C" void kernel_launch(void *const *d_in, const int *in_sizes, int n_in,
                              void *d_out, int out_size) {
    const float     *x      = (const float *)d_in[0];
    const long long *ei     = (const long long *)d_in[1];
    const float     *e      = (const float *)d_in[2];
    const float     *fR_W1  = (const float *)d_in[3];
    const float     *fR_b1  = (const float *)d_in[4];
    const float     *fR_W2  = (const float *)d_in[5];
    const float     *fR_b2  = (const float *)d_in[6];
    const float     *fO_W1  = (const float *)d_in[7];
    const float     *fO_b1  = (const float *)d_in[8];
    const float     *fO_W2  = (const float *)d_in[9];
    const float     *fO_b2  = (const float *)d_in[10];

    float *outX = (float *)d_out;                       // x_new: [50000,16]
    float *outE = (float *)d_out + (size_t)N_NODES * 16; // e_new: [1600000,16]

    probe_kernel<<<1, 256>>>((const int *)ei);

    int pre_items = N_NODES * 12;
    int zero_items = N_NODES * 16 / 4;
    int pre_threads = pre_items > zero_items ? pre_items : zero_items;
    pre_kernel<<<(pre_threads + 127) / 128, 128>>>(x, fR_W1, fR_b1, fO_W1, fO_b1);

    edge_kernel<<<N_EDGES / 128, 128>>>(ei, e, fR_W1, fR_W2, fR_b2, outE);

    node_kernel<<<(N_NODES + 127) / 128, 128>>>(fO_W1, fO_W2, fO_b2, outX);
}

// round 6
// speedup vs baseline: 1.2782x; 1.2782x over previous
#include <cuda_runtime.h>
#include <cstdint>
#include <cstddef>

#define N_NODES 50000
#define N_EDGES 1600000
#define N_TILES (N_EDGES / 128)
#define PITCH 52   /* stage row pitch in floats */
#define TPITCH 20  /* transpose buffer pitch in floats */

typedef unsigned long long u64;
typedef unsigned int u32;

// ---------------- scratch (static device globals; no allocation) ----------------
__device__ __align__(16) float g_gx[(size_t)N_NODES * 64];   // x @ fO_W1[0:16,:] + fO_b1
__device__ __align__(16) float g_agg[(size_t)N_NODES * 16];  // scatter-sum of e_new
__device__ int g_is64;

// ================= helpers =================
__device__ __forceinline__ u32 tf32r(float f) {
    u32 r; asm("cvt.rna.tf32.f32 %0, %1;" : "=r"(r) : "f"(f)); return r;
}
__device__ __forceinline__ void mma_tf32(float *c, u32 a0, u32 a1, u32 a2, u32 a3,
                                         u32 b0, u32 b1) {
    asm volatile(
        "mma.sync.aligned.m16n8k8.row.col.f32.tf32.tf32.f32 "
        "{%0,%1,%2,%3}, {%4,%5,%6,%7}, {%8,%9}, {%0,%1,%2,%3};"
        : "+f"(c[0]), "+f"(c[1]), "+f"(c[2]), "+f"(c[3])
        : "r"(a0), "r"(a1), "r"(a2), "r"(a3), "r"(b0), "r"(b1));
}

// ---------------- probe: is edge_index int64 or int32? (hardened) ----------------
__global__ void probe_kernel(const int *__restrict__ ei32) {
    __shared__ int nz;
    if (threadIdx.x == 0) nz = 0;
    __syncthreads();
    // int64 little-endian with values < 50000 -> ALL odd 32-bit words are zero.
    // int32 -> odd words are node ids, overwhelmingly nonzero.
    if (ei32[threadIdx.x * 2 + 1] != 0) atomicAdd(&nz, 1);
    __syncthreads();
    if (threadIdx.x == 0) g_is64 = (nz == 0);
}

// ================= edge kernel: mma.sync tf32 =================
__global__ void __launch_bounds__(128, 4) edge_kernel(
    const long long *__restrict__ ei64,
    const float *__restrict__ e,
    const float *__restrict__ x,
    const float *__restrict__ fR_W1, const float *__restrict__ fR_b1,
    const float *__restrict__ fR_W2, const float *__restrict__ fR_b2,
    float *__restrict__ outE) {
    __shared__ u32 sStage[128 * PITCH];   // gather stage; reused as transpose buf
    __shared__ u32 sB1[48 * 64];          // frag-major: ((ks*8+nf)*32+lane)*2 + {0,1}
    __shared__ u32 sB2[16 * 64];          // ((ks*2+nf)*32+lane)*2 + {0,1}
    __shared__ float sb1[64];
    __shared__ float sb2[16];
    __shared__ int sSrc[128], sDst[128];

    const int tid = threadIdx.x;
    const int w = tid >> 5, l = tid & 31;
    const int q = l >> 2, m = l & 3;
    const int is64 = g_is64;
    const int e0 = blockIdx.x * 128;

    // ---- stage weight fragments (col-major B: b0=(k=m, n=q), b1=(k=m+4, n=q)) ----
    for (int f = w; f < 48; f += 4) {
        int ks = f >> 3, nf = f & 7;
        sB1[(f * 32 + l) * 2 + 0] = tf32r(fR_W1[(ks * 8 + m) * 64 + nf * 8 + q]);
        sB1[(f * 32 + l) * 2 + 1] = tf32r(fR_W1[(ks * 8 + m + 4) * 64 + nf * 8 + q]);
    }
    for (int f = w; f < 16; f += 4) {
        int ks = f >> 1, nf = f & 1;
        sB2[(f * 32 + l) * 2 + 0] = tf32r(fR_W2[(ks * 8 + m) * 16 + nf * 8 + q]);
        sB2[(f * 32 + l) * 2 + 1] = tf32r(fR_W2[(ks * 8 + m + 4) * 16 + nf * 8 + q]);
    }
    if (tid < 64) sb1[tid] = fR_b1[tid];
    if (tid < 16) sb2[tid] = fR_b2[tid];

    // ---- edge indices ----
    int src, dst;
    if (is64) {
        src = (int)ei64[e0 + tid];
        dst = (int)ei64[N_EDGES + e0 + tid];
    } else {
        const int *ei32 = (const int *)ei64;
        src = ei32[e0 + tid];
        dst = ei32[N_EDGES + e0 + tid];
    }
    sSrc[tid] = src;
    sDst[tid] = dst;
    __syncthreads();

    // ---- gather stage[el][0:16]=x[dst], [16:32]=x[src], [32:48]=e (tf32-rounded) ----
    {
        const float4 *x4 = (const float4 *)x;
        const float4 *e4 = (const float4 *)e;
        const int elb = tid >> 2, qq = tid & 3;
#pragma unroll
        for (int p = 0; p < 4; p++) {
            int el = elb + p * 32;
            float4 vd = x4[(size_t)sDst[el] * 4 + qq];
            float4 vs = x4[(size_t)sSrc[el] * 4 + qq];
            float4 ve = e4[(size_t)(e0 + el) * 4 + qq];
            u32 *row = &sStage[el * PITCH];
            *(uint4 *)&row[qq * 4]      = make_uint4(tf32r(vd.x), tf32r(vd.y), tf32r(vd.z), tf32r(vd.w));
            *(uint4 *)&row[16 + qq * 4] = make_uint4(tf32r(vs.x), tf32r(vs.y), tf32r(vs.z), tf32r(vs.w));
            *(uint4 *)&row[32 + qq * 4] = make_uint4(tf32r(ve.x), tf32r(ve.y), tf32r(ve.z), tf32r(ve.w));
        }
    }
    __syncthreads();

    // ---- layer 1: C[s][nf] = in[32x48] @ W1 + b1 ----
    float C[2][8][4];
#pragma unroll
    for (int s = 0; s < 2; s++)
#pragma unroll
        for (int nf = 0; nf < 8; nf++) {
            float bv0 = sb1[nf * 8 + 2 * m], bv1 = sb1[nf * 8 + 2 * m + 1];
            C[s][nf][0] = bv0; C[s][nf][1] = bv1; C[s][nf][2] = bv0; C[s][nf][3] = bv1;
        }
#pragma unroll
    for (int ks = 0; ks < 6; ks++) {
        u32 Bf0[8], Bf1[8];
#pragma unroll
        for (int nf = 0; nf < 8; nf++) {
            uint2 bv = *(const uint2 *)&sB1[((ks * 8 + nf) * 32 + l) * 2];
            Bf0[nf] = bv.x; Bf1[nf] = bv.y;
        }
#pragma unroll
        for (int s = 0; s < 2; s++) {
            int rb = w * 32 + s * 16 + q;
            u32 a0 = sStage[rb * PITCH + ks * 8 + m];
            u32 a1 = sStage[(rb + 8) * PITCH + ks * 8 + m];
            u32 a2 = sStage[rb * PITCH + ks * 8 + m + 4];
            u32 a3 = sStage[(rb + 8) * PITCH + ks * 8 + m + 4];
#pragma unroll
            for (int nf = 0; nf < 8; nf++)
                mma_tf32(C[s][nf], a0, a1, a2, a3, Bf0[nf], Bf1[nf]);
        }
    }

    // ---- layer 2: relu -> tf32 -> (shuffle D->A frags) -> @W2 + b2 ----
    float C2[2][2][4];
#pragma unroll
    for (int s = 0; s < 2; s++)
#pragma unroll
        for (int nf = 0; nf < 2; nf++) {
            float bv0 = sb2[nf * 8 + 2 * m], bv1 = sb2[nf * 8 + 2 * m + 1];
            C2[s][nf][0] = bv0; C2[s][nf][1] = bv1; C2[s][nf][2] = bv0; C2[s][nf][3] = bv1;
        }
    const int l0 = (l & ~3) | (m >> 1);
    const int l1 = l0 + 2;
    const bool pr = (m & 1);
#pragma unroll
    for (int s = 0; s < 2; s++) {
        u32 H[8][4];
#pragma unroll
        for (int nf = 0; nf < 8; nf++)
#pragma unroll
            for (int r = 0; r < 4; r++)
                H[nf][r] = tf32r(fmaxf(C[s][nf][r], 0.0f));
#pragma unroll
        for (int ks = 0; ks < 8; ks++) {
            u32 u0 = __shfl_sync(0xffffffffu, H[ks][0], l0);
            u32 u1 = __shfl_sync(0xffffffffu, H[ks][1], l0);
            u32 u2 = __shfl_sync(0xffffffffu, H[ks][2], l0);
            u32 u3 = __shfl_sync(0xffffffffu, H[ks][3], l0);
            u32 v0 = __shfl_sync(0xffffffffu, H[ks][0], l1);
            u32 v1 = __shfl_sync(0xffffffffu, H[ks][1], l1);
            u32 v2 = __shfl_sync(0xffffffffu, H[ks][2], l1);
            u32 v3 = __shfl_sync(0xffffffffu, H[ks][3], l1);
            u32 a0 = pr ? u1 : u0;
            u32 a1 = pr ? u3 : u2;
            u32 a2 = pr ? v1 : v0;
            u32 a3 = pr ? v3 : v2;
            uint2 bf0 = *(const uint2 *)&sB2[((ks * 2 + 0) * 32 + l) * 2];
            uint2 bf1 = *(const uint2 *)&sB2[((ks * 2 + 1) * 32 + l) * 2];
            mma_tf32(C2[s][0], a0, a1, a2, a3, bf0.x, bf0.y);
            mma_tf32(C2[s][1], a0, a1, a2, a3, bf1.x, bf1.y);
        }
    }

    // ---- epilogue: transpose D2 to thread-per-edge, store + scatter ----
    __syncthreads();  // all layer-1 A reads of sStage are done block-wide
    float *T = (float *)sStage;
#pragma unroll
    for (int s = 0; s < 2; s++)
#pragma unroll
        for (int nf = 0; nf < 2; nf++) {
            int row = w * 32 + s * 16 + q;
            int col = nf * 8 + 2 * m;
            *(float2 *)&T[row * TPITCH + col] = make_float2(C2[s][nf][0], C2[s][nf][1]);
            *(float2 *)&T[(row + 8) * TPITCH + col] = make_float2(C2[s][nf][2], C2[s][nf][3]);
        }
    __syncwarp();
    {
        int el = w * 32 + l;
        const float *tr = &T[el * TPITCH];
        float4 o0 = *(const float4 *)&tr[0];
        float4 o1 = *(const float4 *)&tr[4];
        float4 o2 = *(const float4 *)&tr[8];
        float4 o3 = *(const float4 *)&tr[12];
        float4 *op = (float4 *)(outE + (size_t)(e0 + el) * 16);
        op[0] = o0; op[1] = o1; op[2] = o2; op[3] = o3;
        // scalar atomics (runtime-proven path from round 1)
        float *ag = g_agg + (size_t)sDst[el] * 16;
        atomicAdd(ag + 0,  o0.x); atomicAdd(ag + 1,  o0.y);
        atomicAdd(ag + 2,  o0.z); atomicAdd(ag + 3,  o0.w);
        atomicAdd(ag + 4,  o1.x); atomicAdd(ag + 5,  o1.y);
        atomicAdd(ag + 6,  o1.z); atomicAdd(ag + 7,  o1.w);
        atomicAdd(ag + 8,  o2.x); atomicAdd(ag + 9,  o2.y);
        atomicAdd(ag + 10, o2.z); atomicAdd(ag + 11, o2.w);
        atomicAdd(ag + 12, o3.x); atomicAdd(ag + 13, o3.y);
        atomicAdd(ag + 14, o3.z); atomicAdd(ag + 15, o3.w);
    }
}

// ================= node-side path (scalar FFMA2) =================
__device__ __forceinline__ u64 ffma2(u64 a, u64 b, u64 c) {
    u64 d; asm("fma.rn.f32x2 %0, %1, %2, %3;" : "=l"(d) : "l"(a), "l"(b), "l"(c)); return d;
}
__device__ __forceinline__ u64 dup2(float a) { u64 r; asm("mov.b64 %0, {%1, %1};" : "=l"(r) : "f"(a)); return r; }
__device__ __forceinline__ float2 unpk(u64 a) { float2 f; asm("mov.b64 {%0, %1}, %2;" : "=f"(f.x), "=f"(f.y) : "l"(a)); return f; }
__device__ __forceinline__ u64 pk(float xx, float yy) { u64 r; asm("mov.b64 %0, {%1, %2};" : "=l"(r) : "f"(xx), "f"(yy)); return r; }
__device__ __forceinline__ void lds2(u64 &a, u64 &b, unsigned addr) {
    asm("ld.shared.v2.u64 {%0, %1}, [%2];" : "=l"(a), "=l"(b) : "r"(addr));
}
__device__ __forceinline__ unsigned sptr(const void *p) { return (unsigned)__cvta_generic_to_shared(p); }

__device__ __forceinline__ void mlp64(u64 *H, const float *av,
                                      unsigned wb1, unsigned wb2, unsigned bb, u64 *O) {
#pragma unroll
    for (int k = 0; k < 16; k++) {
        u64 a2 = dup2(av[k]);
#pragma unroll
        for (int t = 0; t < 16; t++) {
            u64 w0, w1;
            lds2(w0, w1, wb1 + k * 256 + t * 16);
            H[2 * t] = ffma2(a2, w0, H[2 * t]);
            H[2 * t + 1] = ffma2(a2, w1, H[2 * t + 1]);
        }
    }
#pragma unroll
    for (int mm = 0; mm < 32; mm++) {
        float2 v = unpk(H[mm]);
        H[mm] = pk(fmaxf(v.x, 0.f), fmaxf(v.y, 0.f));
    }
#pragma unroll
    for (int c = 0; c < 4; c++) lds2(O[2 * c], O[2 * c + 1], bb + 16 * c);
#pragma unroll
    for (int mm = 0; mm < 32; mm++) {
        float2 hv = unpk(H[mm]);
        u64 a0 = dup2(hv.x);
#pragma unroll
        for (int c = 0; c < 4; c++) {
            u64 w0, w1;
            lds2(w0, w1, wb2 + (2 * mm) * 64 + c * 16);
            O[2 * c] = ffma2(a0, w0, O[2 * c]);
            O[2 * c + 1] = ffma2(a0, w1, O[2 * c + 1]);
        }
        u64 a1 = dup2(hv.y);
#pragma unroll
        for (int c = 0; c < 4; c++) {
            u64 w0, w1;
            lds2(w0, w1, wb2 + (2 * mm + 1) * 64 + c * 16);
            O[2 * c] = ffma2(a1, w0, O[2 * c]);
            O[2 * c + 1] = ffma2(a1, w1, O[2 * c + 1]);
        }
    }
}

// precompute g_gx = x @ fO_W1[0:16,:] + fO_b1, and zero g_agg
__global__ void __launch_bounds__(128) pre_kernel(
    const float *__restrict__ x,
    const float *__restrict__ fO_W1, const float *__restrict__ fO_b1) {
    const int gtid = blockIdx.x * 128 + threadIdx.x;
    if (gtid >= N_NODES * 4) return;
    ((float4 *)g_agg)[gtid] = make_float4(0.f, 0.f, 0.f, 0.f);
    const int n = gtid >> 2;
    const int ch = gtid & 3;

    float xv[16];
    const float4 *x4 = (const float4 *)x;
#pragma unroll
    for (int qq = 0; qq < 4; qq++) {
        float4 v = x4[(size_t)n * 4 + qq];
        xv[4 * qq] = v.x; xv[4 * qq + 1] = v.y; xv[4 * qq + 2] = v.z; xv[4 * qq + 3] = v.w;
    }
    float acc[16];
    {
        const float4 *b4 = (const float4 *)(fO_b1 + ch * 16);
#pragma unroll
        for (int qq = 0; qq < 4; qq++) {
            float4 v = b4[qq];
            acc[4 * qq] = v.x; acc[4 * qq + 1] = v.y; acc[4 * qq + 2] = v.z; acc[4 * qq + 3] = v.w;
        }
    }
#pragma unroll
    for (int k = 0; k < 16; k++) {
        const float4 *wr = (const float4 *)(fO_W1 + k * 64 + ch * 16);
#pragma unroll
        for (int qq = 0; qq < 4; qq++) {
            float4 wv = wr[qq];
            acc[4 * qq]     += xv[k] * wv.x;
            acc[4 * qq + 1] += xv[k] * wv.y;
            acc[4 * qq + 2] += xv[k] * wv.z;
            acc[4 * qq + 3] += xv[k] * wv.w;
        }
    }
    float4 *o4 = (float4 *)(g_gx + (size_t)n * 64 + ch * 16);
#pragma unroll
    for (int qq = 0; qq < 4; qq++) {
        float4 v;
        v.x = acc[4 * qq]; v.y = acc[4 * qq + 1]; v.z = acc[4 * qq + 2]; v.w = acc[4 * qq + 3];
        o4[qq] = v;
    }
}

__global__ void __launch_bounds__(128) node_kernel(
    const float *__restrict__ fO_W1,
    const float *__restrict__ fO_W2,
    const float *__restrict__ fO_b2,
    float *__restrict__ outX) {
    __shared__ float sW1c[1024];  // fO_W1 rows 16..31 (agg part)
    __shared__ float sW2[1024];
    __shared__ float sB2[16];
    const int tid = threadIdx.x;
    {
        const float4 *w1 = (const float4 *)(fO_W1 + 16 * 64);
        const float4 *w2 = (const float4 *)fO_W2;
        ((float4 *)sW1c)[tid] = w1[tid];
        ((float4 *)sW1c)[tid + 128] = w1[tid + 128];
        ((float4 *)sW2)[tid] = w2[tid];
        ((float4 *)sW2)[tid + 128] = w2[tid + 128];
        if (tid < 16) sB2[tid] = fO_b2[tid];
    }
    __syncthreads();
    const int n = blockIdx.x * 128 + tid;
    if (n >= N_NODES) return;

    u64 H[32];
    {
        const float4 *gx4 = (const float4 *)g_gx;
#pragma unroll
        for (int t = 0; t < 16; t++) {
            float4 v = gx4[(size_t)n * 16 + t];
            H[2 * t] = pk(v.x, v.y);
            H[2 * t + 1] = pk(v.z, v.w);
        }
    }
    float av[16];
    {
        const float4 *a4 = (const float4 *)g_agg;
#pragma unroll
        for (int qq = 0; qq < 4; qq++) {
            float4 v = a4[(size_t)n * 4 + qq];
            av[4 * qq] = v.x; av[4 * qq + 1] = v.y; av[4 * qq + 2] = v.z; av[4 * qq + 3] = v.w;
        }
    }
    u64 O[8];
    mlp64(H, av, sptr(sW1c), sptr(sW2), sptr(sB2), O);

    float4 *oX4 = (float4 *)outX;
#pragma unroll
    for (int qq = 0; qq < 4; qq++) {
        float2 v0 = unpk(O[2 * qq]);
        float2 v1 = unpk(O[2 * qq + 1]);
        float4 v;
        v.x = v0.x; v.y = v0.y; v.z = v1.x; v.w = v1.y;
        oX4[(size_t)n * 4 + qq] = v;
    }
}

// ---------------- launch ----------------
extern "C" void kernel_launch(void *const *d_in, const int *in_sizes, int n_in,
                              void *d_out, int out_size) {
    const float     *x     = (const float *)d_in[0];
    const long long *ei    = (const long long *)d_in[1];
    const float     *e     = (const float *)d_in[2];
    const float     *fR_W1 = (const float *)d_in[3];
    const float     *fR_b1 = (const float *)d_in[4];
    const float     *fR_W2 = (const float *)d_in[5];
    const float     *fR_b2 = (const float *)d_in[6];
    const float     *fO_W1 = (const float *)d_in[7];
    const float     *fO_b1 = (const float *)d_in[8];
    const float     *fO_W2 = (const float *)d_in[9];
    const float     *fO_b2 = (const float *)d_in[10];

    float *outX = (float *)d_out;                         // x_new [50000,16]
    float *outE = (float *)d_out + (size_t)N_NODES * 16;  // e_new [1600000,16]

    probe_kernel<<<1, 256>>>((const int *)ei);
    pre_kernel<<<(N_NODES * 4 + 127) / 128, 128>>>(x, fO_W1, fO_b1);
    edge_kernel<<<N_TILES, 128>>>(ei, e, x, fR_W1, fR_b1, fR_W2, fR_b2, outE);
    node_kernel<<<(N_NODES + 127) / 128, 128>>>(fO_W1, fO_W2, fO_b2, outX);
}